// round 14
// baseline (speedup 1.0000x reference)
#include <cuda_runtime.h>
#include <cuda_bf16.h>
#include <math.h>
#include <stdint.h>

// ---------------- problem constants ----------------
#define BATCH   16
#define TOPN    4
#define NA      1614
#define OUT_S   224
#define IM_S    448
#define PAD_S   224
#define HP_S    896

#define NPART   (BATCH*TOPN*3*OUT_S*OUT_S)   // 9,633,792
#define OFF_TIDX  NPART
#define OFF_TPROB (NPART + BATCH*TOPN)
#define OFF_SCORE (NPART + 2*BATCH*TOPN)

#define KSPLIT  9
#define NCHUNK  32
#define NP1     (BATCH*128*196)

#define N2      (BATCH*128*49)
#define N3      (BATCH*128*16)

// ---------------- scratch ----------------
__device__ float g_part1[(size_t)KSPLIT * NP1];
__device__ float g_d1[NP1];
__device__ float g_p2[(size_t)9 * N2];
__device__ float g_d2[N2];
__device__ float g_p3[(size_t)9 * N3];
__device__ float g_score[BATCH*NA];
__device__ int   g_topidx[BATCH*TOPN];

// bf16 hi/lo prepped operands (zero-initialized; plane borders stay zero)
__device__ __nv_bfloat16 g_wh[(size_t)9 * 128 * 2048];
__device__ __nv_bfloat16 g_wl[(size_t)9 * 128 * 2048];
__device__ __nv_bfloat16 g_ih[(size_t)BATCH * 288 * 2048];
__device__ __nv_bfloat16 g_il[(size_t)BATCH * 288 * 2048];
__device__ __nv_bfloat16 g_w2h[(size_t)9 * 128 * 128];
__device__ __nv_bfloat16 g_w2l[(size_t)9 * 128 * 128];
__device__ __nv_bfloat16 g_w3h[(size_t)9 * 128 * 128];
__device__ __nv_bfloat16 g_w3l[(size_t)9 * 128 * 128];
__device__ __nv_bfloat16 g_d1h[(size_t)BATCH * 256 * 128];
__device__ __nv_bfloat16 g_d1l[(size_t)BATCH * 256 * 128];
__device__ __nv_bfloat16 g_d2h[(size_t)BATCH * 256 * 128];
__device__ __nv_bfloat16 g_d2l[(size_t)BATCH * 256 * 128];

__device__ __forceinline__ float neg_inf() { return __int_as_float(0xff800000); }

__device__ __forceinline__ uint32_t smem_to_u32(const void* p) {
    uint32_t a;
    asm("{ .reg .u64 t; cvta.to.shared.u64 t, %1; cvt.u32.u64 %0, t; }"
        : "=r"(a) : "l"(p));
    return a;
}
__device__ __forceinline__ void cpa16(uint32_t dst, const void* src) {
    asm volatile("cp.async.cg.shared.global [%0], [%1], 16;"
                 :: "r"(dst), "l"(src) : "memory");
}
__device__ __forceinline__ void ldsm_x4(uint32_t& r0, uint32_t& r1, uint32_t& r2, uint32_t& r3,
                                        uint32_t addr) {
    asm volatile("ldmatrix.sync.aligned.m8n8.x4.shared.b16 {%0,%1,%2,%3}, [%4];"
                 : "=r"(r0), "=r"(r1), "=r"(r2), "=r"(r3) : "r"(addr));
}
__device__ __forceinline__ void ldsm_x2(uint32_t& r0, uint32_t& r1, uint32_t addr) {
    asm volatile("ldmatrix.sync.aligned.m8n8.x2.shared.b16 {%0,%1}, [%2];"
                 : "=r"(r0), "=r"(r1) : "r"(addr));
}
__device__ __forceinline__ void mma16816(float* c, uint32_t a0, uint32_t a1, uint32_t a2,
                                         uint32_t a3, uint32_t b0, uint32_t b1) {
    asm volatile("mma.sync.aligned.m16n8k16.row.col.f32.bf16.bf16.f32 "
                 "{%0,%1,%2,%3}, {%4,%5,%6,%7}, {%8,%9}, {%0,%1,%2,%3};"
                 : "+f"(c[0]), "+f"(c[1]), "+f"(c[2]), "+f"(c[3])
                 : "r"(a0), "r"(a1), "r"(a2), "r"(a3), "r"(b0), "r"(b1));
}
__device__ __forceinline__ void bfsplit(float v, __nv_bfloat16& h, __nv_bfloat16& l) {
    h = __float2bfloat16_rn(v);
    l = __float2bfloat16_rn(v - __bfloat162float(h));
}
__device__ __forceinline__ uint32_t pkbf(__nv_bfloat16 a, __nv_bfloat16 b) {
    return (uint32_t)__bfloat16_as_ushort(a) | ((uint32_t)__bfloat16_as_ushort(b) << 16);
}

// ====== prep_all: weights (blocks 0..1151) + input planes (1152..2175) ====
__global__ void prep_all(const float* __restrict__ w1,
                         const float* __restrict__ w2,
                         const float* __restrict__ w3,
                         const float* __restrict__ in)
{
    int blk = blockIdx.x;
    if (blk < 1024) {
        int idx = blk * 256 + threadIdx.x;
        int oc = idx >> 11, ic = idx & 2047;
        const float* src = w1 + (size_t)oc * 18432 + (size_t)ic * 9;
#pragma unroll
        for (int t = 0; t < 9; t++) {
            __nv_bfloat16 h, l;
            bfsplit(__ldg(&src[t]), h, l);
            size_t d = ((size_t)t * 128 + oc) * 2048 + ic;
            g_wh[d] = h; g_wl[d] = l;
        }
    } else if (blk < 1152) {
        int idx = (blk - 1024) * 256 + threadIdx.x;
        int which = idx >> 14, r = idx & 16383;
        int oc = r >> 7, ic = r & 127;
        const float* src = (which ? w3 : w2) + (size_t)(oc * 128 + ic) * 9;
        __nv_bfloat16* dh = which ? g_w3h : g_w2h;
        __nv_bfloat16* dl = which ? g_w3l : g_w2l;
#pragma unroll
        for (int t = 0; t < 9; t++) {
            __nv_bfloat16 h, l;
            bfsplit(__ldg(&src[t]), h, l);
            size_t d = ((size_t)t * 128 + oc) * 128 + ic;
            dh[d] = h; dl[d] = l;
        }
    } else {
        __shared__ float s_in[32][197];
        int iidx = blk - 1152;
        const int icb = iidx & 63;
        const int b   = iidx >> 6;
        const int tid = threadIdx.x;

        const float* src = in + ((size_t)b * 2048 + icb * 32) * 196;
        for (int i = tid; i < 32 * 196; i += 256)
            s_in[i / 196][i % 196] = __ldg(&src[i]);
        __syncthreads();

        for (int i = tid; i < 288 * 16; i += 256) {
            int pos = i >> 4, icp = i & 15;
            int py = pos / 18, px = pos % 18;
            int iy = py - 1, ix = px - 1;
            float v0 = 0.f, v1 = 0.f;
            if ((unsigned)iy < 14u && (unsigned)ix < 14u) {
                v0 = s_in[icp * 2][iy * 14 + ix];
                v1 = s_in[icp * 2 + 1][iy * 14 + ix];
            }
            __nv_bfloat16 h0, l0, h1, l1;
            bfsplit(v0, h0, l0); bfsplit(v1, h1, l1);
            size_t d = ((size_t)b * 288 + pos) * 2048 + icb * 32 + icp * 2;
            *(uint32_t*)&g_ih[d] = pkbf(h0, h1);
            *(uint32_t*)&g_il[d] = pkbf(l0, l1);
        }
    }
}

// ================= conv1 via mma.sync: 512 threads / 16 warps =============
// Grid (9 taps, 16 batches). M=128, N=208 (196 valid), K=2048, 32 chunks.
// Warp tile: 16 oc x 104 n (mrow=wid%8, ncol=wid/8) -> 4 warps/SMSP to hide
// LDSM latency. Per-accumulator K/pass order unchanged -> bit-identical.
#define SA_H   0
#define SA_L   18432
#define SB_H   36864
#define SB_L   66816
#define STG_SZ 96768
#define SM_TOT (2 * STG_SZ)

__global__ void __launch_bounds__(512) conv1_mma()
{
    extern __shared__ __align__(16) char smem[];
    const uint32_t sb = smem_to_u32(smem);
    const int tid = threadIdx.x, wid = tid >> 5, lane = tid & 31;
    const int t = blockIdx.x, b = blockIdx.y;
    const int dy = t / 3 - 1, dx = t % 3 - 1;

    const int mrow = wid & 7;    // oc 16-block
    const int ncol = wid >> 3;   // 104-wide n block (13 tiles)

    float acc[13][4];
#pragma unroll
    for (int nt = 0; nt < 13; nt++)
#pragma unroll
        for (int i = 0; i < 4; i++) acc[nt][i] = 0.f;

    const __nv_bfloat16* ah0 = g_wh + ((size_t)t * 128) * 2048;
    const __nv_bfloat16* al0 = g_wl + ((size_t)t * 128) * 2048;
    const __nv_bfloat16* bh0 = g_ih + (size_t)b * 288 * 2048;
    const __nv_bfloat16* bl0 = g_il + (size_t)b * 288 * 2048;

    auto fill = [&](int stage, int c) {
        const uint32_t s0 = sb + stage * STG_SZ;
        const int kof = c * 64;
        for (int idx = tid; idx < 1024; idx += 512) {
            int row = idx >> 3, seg = idx & 7;
            uint32_t off = (uint32_t)(row * 144 + seg * 16);
            size_t so = (size_t)row * 2048 + kof + seg * 8;
            cpa16(s0 + SA_H + off, ah0 + so);
            cpa16(s0 + SA_L + off, al0 + so);
        }
        for (int idx = tid; idx < 1664; idx += 512) {
            int row = idx >> 3, seg = idx & 7;
            int pos = 0;
            if (row < 196) {
                int y = row / 14, x = row - y * 14;
                pos = (y + dy + 1) * 18 + (x + dx + 1);
            }
            uint32_t off = (uint32_t)(row * 144 + seg * 16);
            size_t so = (size_t)pos * 2048 + kof + seg * 8;
            cpa16(s0 + SB_H + off, bh0 + so);
            cpa16(s0 + SB_L + off, bl0 + so);
        }
        asm volatile("cp.async.commit_group;" ::: "memory");
    };

    const uint32_t aRow = (uint32_t)(lane & 15);
    const uint32_t aHalf = (uint32_t)(lane >> 4) * 16;
    const uint32_t bRow = (uint32_t)(lane & 7);
    const uint32_t bHalf = (uint32_t)((lane >> 3) & 1) * 16;

    fill(0, 0);
    int s = 0;
    for (int c = 0; c < NCHUNK; c++) {
        asm volatile("cp.async.wait_group 0;" ::: "memory");
        __syncthreads();
        if (c + 1 < NCHUNK) fill(s ^ 1, c + 1);

        const uint32_t s0 = sb + s * STG_SZ;
#pragma unroll
        for (int kkstep = 0; kkstep < 4; kkstep++) {
            const uint32_t kb = (uint32_t)kkstep * 32;
            uint32_t ah[4], al[4];
            uint32_t ra = (uint32_t)((mrow * 16 + aRow) * 144) + kb + aHalf;
            ldsm_x4(ah[0], ah[1], ah[2], ah[3], s0 + SA_H + ra);
            ldsm_x4(al[0], al[1], al[2], al[3], s0 + SA_L + ra);
#pragma unroll
            for (int nt = 0; nt < 13; nt++) {
                uint32_t rb = (uint32_t)((ncol * 104 + nt * 8 + bRow) * 144) + kb + bHalf;
                uint32_t bhr0, bhr1, blr0, blr1;
                ldsm_x2(bhr0, bhr1, s0 + SB_H + rb);
                ldsm_x2(blr0, blr1, s0 + SB_L + rb);
                mma16816(acc[nt], ah[0], ah[1], ah[2], ah[3], bhr0, bhr1);
                mma16816(acc[nt], ah[0], ah[1], ah[2], ah[3], blr0, blr1);
                mma16816(acc[nt], al[0], al[1], al[2], al[3], bhr0, bhr1);
            }
        }
        s ^= 1;
        __syncthreads();
    }

    const int r = lane >> 2, q = lane & 3;
    float* pp = g_part1 + (size_t)t * NP1 + ((size_t)b * 128) * 196;
    const int oc0 = mrow * 16 + r;
#pragma unroll
    for (int nt = 0; nt < 13; nt++) {
        int n0 = ncol * 104 + nt * 8 + 2 * q;
        if (n0 < 196) {
            pp[(size_t)oc0 * 196 + n0]       = acc[nt][0];
            pp[(size_t)(oc0 + 8) * 196 + n0] = acc[nt][2];
        }
        if (n0 + 1 < 196) {
            pp[(size_t)oc0 * 196 + n0 + 1]       = acc[nt][1];
            pp[(size_t)(oc0 + 8) * 196 + n0 + 1] = acc[nt][3];
        }
    }
}

// ====== finalize1: split-K reduce + bias + relu + write d1 planes =========
__global__ void finalize1_kernel(const float* __restrict__ bias)
{
    int n = blockIdx.x * 256 + threadIdx.x;
    if (n >= NP1) return;
    float s = 0.f;
#pragma unroll
    for (int k = 0; k < KSPLIT; k++) s += g_part1[(size_t)k * NP1 + n];
    int p = n % 196;
    int oc = (n / 196) & 127;
    int b = n / (196 * 128);
    float v = fmaxf(s + __ldg(&bias[oc]), 0.f);
    g_d1[n] = v;
    int pos = (p / 14 + 1) * 16 + (p % 14 + 1);
    __nv_bfloat16 h, l;
    bfsplit(v, h, l);
    size_t d = ((size_t)b * 256 + pos) * 128 + oc;
    g_d1h[d] = h;
    g_d1l[d] = l;
}

// ================= conv23_mma =============================================
#define C23_A_H  0
#define C23_A_L  34816
#define C23_B_H  69632
#define C23_B_L  87040
#define C23_TOT  104448

__global__ void __launch_bounds__(256) conv23_mma(const __nv_bfloat16* __restrict__ wh,
                                                  const __nv_bfloat16* __restrict__ wl,
                                                  const __nv_bfloat16* __restrict__ inh,
                                                  const __nv_bfloat16* __restrict__ inl,
                                                  float* __restrict__ part,
                                                  int OW, int NVALID)
{
    extern __shared__ __align__(16) char smem[];
    const uint32_t sb = smem_to_u32(smem);
    const int tid = threadIdx.x, wid = tid >> 5, lane = tid & 31;
    const int t = blockIdx.x, b = blockIdx.y;
    const int dy = t / 3 - 1, dx = t % 3 - 1;
    const int mrow = wid & 3;
    const int ncol = wid >> 2;

    const __nv_bfloat16* ah0 = wh + (size_t)t * 128 * 128;
    const __nv_bfloat16* al0 = wl + (size_t)t * 128 * 128;
    const __nv_bfloat16* bh0 = inh + (size_t)b * 256 * 128;
    const __nv_bfloat16* bl0 = inl + (size_t)b * 256 * 128;

    for (int idx = tid; idx < 2048; idx += 256) {
        int row = idx >> 4, seg = idx & 15;
        uint32_t off = (uint32_t)(row * 272 + seg * 16);
        size_t so = (size_t)row * 128 + seg * 8;
        cpa16(sb + C23_A_H + off, ah0 + so);
        cpa16(sb + C23_A_L + off, al0 + so);
    }
    for (int idx = tid; idx < 1024; idx += 256) {
        int row = idx >> 4, seg = idx & 15;
        int pos = 0;
        if (row < NVALID) {
            int oy = row / OW, ox = row % OW;
            pos = (2 * oy + dy + 1) * 16 + (2 * ox + dx + 1);
        }
        uint32_t off = (uint32_t)(row * 272 + seg * 16);
        size_t so = (size_t)pos * 128 + seg * 8;
        cpa16(sb + C23_B_H + off, bh0 + so);
        cpa16(sb + C23_B_L + off, bl0 + so);
    }
    asm volatile("cp.async.commit_group;" ::: "memory");
    asm volatile("cp.async.wait_group 0;" ::: "memory");
    __syncthreads();

    float acc[2][4][4];
#pragma unroll
    for (int mt = 0; mt < 2; mt++)
#pragma unroll
        for (int nt = 0; nt < 4; nt++)
#pragma unroll
            for (int i = 0; i < 4; i++) acc[mt][nt][i] = 0.f;

    const uint32_t aRow = (uint32_t)(lane & 15);
    const uint32_t aHalf = (uint32_t)(lane >> 4) * 16;
    const uint32_t bRow = (uint32_t)(lane & 7);
    const uint32_t bHalf = (uint32_t)((lane >> 3) & 1) * 16;

#pragma unroll
    for (int kkstep = 0; kkstep < 8; kkstep++) {
        const uint32_t kb = (uint32_t)kkstep * 32;
        uint32_t ah[2][4], al[2][4];
#pragma unroll
        for (int mt = 0; mt < 2; mt++) {
            uint32_t ra = (uint32_t)((mrow * 32 + mt * 16 + aRow) * 272) + kb + aHalf;
            ldsm_x4(ah[mt][0], ah[mt][1], ah[mt][2], ah[mt][3], sb + C23_A_H + ra);
            ldsm_x4(al[mt][0], al[mt][1], al[mt][2], al[mt][3], sb + C23_A_L + ra);
        }
#pragma unroll
        for (int nt = 0; nt < 4; nt++) {
            uint32_t rb = (uint32_t)((ncol * 32 + nt * 8 + bRow) * 272) + kb + bHalf;
            uint32_t bhr0, bhr1, blr0, blr1;
            ldsm_x2(bhr0, bhr1, sb + C23_B_H + rb);
            ldsm_x2(blr0, blr1, sb + C23_B_L + rb);
#pragma unroll
            for (int mt = 0; mt < 2; mt++) {
                mma16816(acc[mt][nt], ah[mt][0], ah[mt][1], ah[mt][2], ah[mt][3], bhr0, bhr1);
                mma16816(acc[mt][nt], ah[mt][0], ah[mt][1], ah[mt][2], ah[mt][3], blr0, blr1);
                mma16816(acc[mt][nt], al[mt][0], al[mt][1], al[mt][2], al[mt][3], bhr0, bhr1);
            }
        }
    }

    const int r = lane >> 2, q = lane & 3;
    float* pp = part + ((size_t)t * BATCH + b) * 128 * NVALID;
#pragma unroll
    for (int mt = 0; mt < 2; mt++) {
        int oc0 = mrow * 32 + mt * 16 + r;
#pragma unroll
        for (int nt = 0; nt < 4; nt++) {
            int n0 = ncol * 32 + nt * 8 + 2 * q;
            if (n0 < NVALID) {
                pp[(size_t)oc0 * NVALID + n0]       = acc[mt][nt][0];
                pp[(size_t)(oc0 + 8) * NVALID + n0] = acc[mt][nt][2];
            }
            if (n0 + 1 < NVALID) {
                pp[(size_t)oc0 * NVALID + n0 + 1]       = acc[mt][nt][1];
                pp[(size_t)(oc0 + 8) * NVALID + n0 + 1] = acc[mt][nt][3];
            }
        }
    }
}

// ====== reduce2: 9-way reduce + bias + relu + write d2 planes =============
__global__ void reduce2_kernel(const float* __restrict__ bias)
{
    int n = blockIdx.x * 256 + threadIdx.x;
    if (n >= N2) return;
    float s = __ldg(&bias[(n / 49) & 127]);
#pragma unroll
    for (int k = 0; k < 9; k++) s += g_p2[(size_t)k * N2 + n];
    float v = fmaxf(s, 0.f);
    g_d2[n] = v;
    int p = n % 49;
    int oc = (n / 49) & 127;
    int b = n / (49 * 128);
    int pos = (p / 7 + 1) * 16 + (p % 7 + 1);
    __nv_bfloat16 h, l;
    bfsplit(v, h, l);
    size_t d = ((size_t)b * 256 + pos) * 128 + oc;
    g_d2h[d] = h;
    g_d2l[d] = l;
}

// ====== tidy: 1x1 convs -> scores; d3 branch fuses the 9-way reduce =======
__global__ void tidy_kernel(const float* __restrict__ wt1, const float* __restrict__ bt1,
                            const float* __restrict__ wt2, const float* __restrict__ bt2,
                            const float* __restrict__ wt3, const float* __restrict__ bt3,
                            const float* __restrict__ b3,
                            float* __restrict__ out)
{
    int n = blockIdx.x * 256 + threadIdx.x;
    if (n >= BATCH * NA) return;
    int b = n / NA, j = n % NA;
    float acc;
    if (j < 1470) {
        const float* src; const float* wt; float bias; int c, p, stride;
        if (j < 1176) {
            c = j / 196; p = j % 196;
            src = g_d1 + (size_t)b * 128 * 196; stride = 196;
            wt = wt1; bias = __ldg(&bt1[c]);
        } else {
            int jj = j - 1176; c = jj / 49; p = jj % 49;
            src = g_d2 + (size_t)b * 128 * 49; stride = 49;
            wt = wt2; bias = __ldg(&bt2[c]);
        }
        const float4* wv = (const float4*)(wt + (size_t)c * 128);
        float a0 = 0.f, a1 = 0.f, a2 = 0.f, a3 = 0.f;
#pragma unroll 8
        for (int i = 0; i < 32; i++) {
            float4 w4 = __ldg(&wv[i]);
            int ic = 4 * i;
            a0 = fmaf(src[(size_t)(ic + 0) * stride + p], w4.x, a0);
            a1 = fmaf(src[(size_t)(ic + 1) * stride + p], w4.y, a1);
            a2 = fmaf(src[(size_t)(ic + 2) * stride + p], w4.z, a2);
            a3 = fmaf(src[(size_t)(ic + 3) * stride + p], w4.w, a3);
        }
        acc = bias + ((a0 + a1) + (a2 + a3));
    } else {
        // d3 branch: reduce g_p3 on the fly (same order: bias, k=0..8, relu)
        int jj = j - 1470;
        int c = jj / 16, p = jj % 16;
        const float* wv = wt3 + (size_t)c * 128;
        acc = __ldg(&bt3[c]);
        for (int ic = 0; ic < 128; ic++) {
            float s = __ldg(&b3[ic]);
            size_t base = ((size_t)b * 128 + ic) * 16 + p;
#pragma unroll
            for (int k = 0; k < 9; k++) s += g_p3[(size_t)k * N3 + base];
            acc = fmaf(fmaxf(s, 0.f), __ldg(&wv[ic]), acc);
        }
    }
    g_score[n] = acc;
    out[OFF_SCORE + n] = acc;
}

// ================= greedy NMS (warp-shuffle reduction) =====================
__global__ void nms_kernel(const int* __restrict__ anchors, float* __restrict__ out)
{
    int b = blockIdx.x, tid = threadIdx.x;
    const int lane = tid & 31, warp = tid >> 5;
    __shared__ float s[NA];
    __shared__ float swv[8];
    __shared__ int   swi[8];
    __shared__ float pbox[4];
    __shared__ float parea;
    __shared__ int   spick;
    __shared__ float sval;

    for (int j = tid; j < NA; j += 256) s[j] = g_score[b * NA + j];
    __syncthreads();

    for (int k = 0; k < TOPN; k++) {
        float bv = neg_inf(); int bi = 0x7fffffff;
        for (int j = tid; j < NA; j += 256) {
            float v = s[j];
            if (v > bv || (v == bv && j < bi)) { bv = v; bi = j; }
        }
#pragma unroll
        for (int off = 16; off > 0; off >>= 1) {
            float v2 = __shfl_down_sync(0xffffffff, bv, off);
            int   i2 = __shfl_down_sync(0xffffffff, bi, off);
            if (v2 > bv || (v2 == bv && i2 < bi)) { bv = v2; bi = i2; }
        }
        if (lane == 0) { swv[warp] = bv; swi[warp] = bi; }
        __syncthreads();
        if (tid == 0) {
            float fv = swv[0]; int fi = swi[0];
#pragma unroll
            for (int w = 1; w < 8; w++) {
                float v2 = swv[w]; int i2 = swi[w];
                if (v2 > fv || (v2 == fv && i2 < fi)) { fv = v2; fi = i2; }
            }
            const int* a = anchors + (size_t)fi * 4;
            pbox[0] = (float)a[0]; pbox[1] = (float)a[1];
            pbox[2] = (float)a[2]; pbox[3] = (float)a[3];
            parea = (pbox[2] - pbox[0]) * (pbox[3] - pbox[1]);
            spick = fi; sval = fv;
            g_topidx[b * TOPN + k] = fi;
            out[OFF_TIDX  + b * TOPN + k] = (float)fi;
            out[OFF_TPROB + b * TOPN + k] = fv;
        }
        __syncthreads();
        float y0 = pbox[0], x0 = pbox[1], y1 = pbox[2], x1 = pbox[3], pa = parea;
        for (int j = tid; j < NA; j += 256) {
            const int* a = anchors + (size_t)j * 4;
            float ay0 = (float)a[0], ax0 = (float)a[1];
            float ay1 = (float)a[2], ax1 = (float)a[3];
            float iy = fmaxf(fminf(ay1, y1) - fmaxf(ay0, y0), 0.f);
            float ix = fmaxf(fminf(ax1, x1) - fmaxf(ax0, x0), 0.f);
            float inter = iy * ix;
            float area  = (ay1 - ay0) * (ax1 - ax0);
            float iou = inter / (area + pa - inter);
            if (iou >= 0.25f) s[j] = neg_inf();
        }
        __syncthreads();
    }
}

// ================= crop + bilinear resize =================================
__device__ __forceinline__ float fetchpix(const float* __restrict__ xb, int yy, int xx)
{
    yy -= PAD_S; xx -= PAD_S;
    if ((unsigned)yy < (unsigned)IM_S && (unsigned)xx < (unsigned)IM_S)
        return __ldg(&xb[(size_t)yy * IM_S + xx]);
    return 0.f;
}

__global__ void crop_kernel(const float* __restrict__ x,
                            const int* __restrict__ anchors,
                            float* __restrict__ out)
{
    const int crop = blockIdx.x;
    const int oy   = blockIdx.y;
    const int ox   = threadIdx.x;
    const int b    = crop >> 2;

    const int pick = g_topidx[crop];
    const int* a = anchors + (size_t)pick * 4;
    float y0 = (float)a[0], x0 = (float)a[1], y1 = (float)a[2], x1 = (float)a[3];

    float ty = (float)oy / 223.0f;
    float tx = (float)ox / 223.0f;
    float ys = y0 + ty * (y1 - y0 - 1.0f);
    float xs = x0 + tx * (x1 - x0 - 1.0f);
    int yi0 = (int)floorf(ys); int yi1 = min(yi0 + 1, HP_S - 1);
    int xi0 = (int)floorf(xs); int xi1 = min(xi0 + 1, HP_S - 1);
    float wy = ys - (float)yi0;
    float wx = xs - (float)xi0;
    float c00 = (1.f - wy) * (1.f - wx);
    float c01 = (1.f - wy) * wx;
    float c10 = wy * (1.f - wx);
    float c11 = wy * wx;

#pragma unroll
    for (int c = 0; c < 3; c++) {
        const float* xb = x + ((size_t)b * 3 + c) * IM_S * IM_S;
        float v = fetchpix(xb, yi0, xi0) * c00
                + fetchpix(xb, yi0, xi1) * c01
                + fetchpix(xb, yi1, xi0) * c10
                + fetchpix(xb, yi1, xi1) * c11;
        out[(((size_t)crop * 3 + c) * OUT_S + oy) * OUT_S + ox] = v;
    }
}

// =========================================================================
extern "C" void kernel_launch(void* const* d_in, const int* in_sizes, int n_in,
                              void* d_out, int out_size)
{
    const float* x    = (const float*)d_in[0];
    const float* rpn  = (const float*)d_in[1];
    const float* w1   = (const float*)d_in[2];
    const float* b1   = (const float*)d_in[3];
    const float* w2   = (const float*)d_in[4];
    const float* b2   = (const float*)d_in[5];
    const float* w3   = (const float*)d_in[6];
    const float* b3   = (const float*)d_in[7];
    const float* wt1  = (const float*)d_in[8];
    const float* bt1  = (const float*)d_in[9];
    const float* wt2  = (const float*)d_in[10];
    const float* bt2  = (const float*)d_in[11];
    const float* wt3  = (const float*)d_in[12];
    const float* bt3  = (const float*)d_in[13];
    const int*   anc  = (const int*)d_in[14];
    float* out = (float*)d_out;

    cudaFuncSetAttribute(conv1_mma, cudaFuncAttributeMaxDynamicSharedMemorySize, SM_TOT);
    cudaFuncSetAttribute(conv23_mma, cudaFuncAttributeMaxDynamicSharedMemorySize, C23_TOT);

    float *p2, *p3;
    cudaGetSymbolAddress((void**)&p2, g_p2);
    cudaGetSymbolAddress((void**)&p3, g_p3);
    __nv_bfloat16 *w2h, *w2l, *w3h, *w3l, *d1h, *d1l, *d2h, *d2l;
    cudaGetSymbolAddress((void**)&w2h, g_w2h);
    cudaGetSymbolAddress((void**)&w2l, g_w2l);
    cudaGetSymbolAddress((void**)&w3h, g_w3h);
    cudaGetSymbolAddress((void**)&w3l, g_w3l);
    cudaGetSymbolAddress((void**)&d1h, g_d1h);
    cudaGetSymbolAddress((void**)&d1l, g_d1l);
    cudaGetSymbolAddress((void**)&d2h, g_d2h);
    cudaGetSymbolAddress((void**)&d2l, g_d2l);

    prep_all<<<2176, 256>>>(w1, w2, w3, rpn);

    conv1_mma<<<dim3(KSPLIT, BATCH), 512, SM_TOT>>>();
    finalize1_kernel<<<(NP1 + 255) / 256, 256>>>(b1);

    conv23_mma<<<dim3(9, BATCH), 256, C23_TOT>>>(w2h, w2l, d1h, d1l, p2, 7, 49);  // ncu slot
    reduce2_kernel<<<(N2 + 255) / 256, 256>>>(b2);

    conv23_mma<<<dim3(9, BATCH), 256, C23_TOT>>>(w3h, w3l, d2h, d2l, p3, 4, 16);

    tidy_kernel<<<(BATCH * NA + 255) / 256, 256>>>(wt1, bt1, wt2, bt2, wt3, bt3, b3, out);
    nms_kernel<<<BATCH, 256>>>(anc, out);
    crop_kernel<<<dim3(BATCH * TOPN, OUT_S), OUT_S>>>(x, anc, out);
}

// round 15
// speedup vs baseline: 1.0818x; 1.0818x over previous
#include <cuda_runtime.h>
#include <cuda_bf16.h>
#include <math.h>
#include <stdint.h>

// ---------------- problem constants ----------------
#define BATCH   16
#define TOPN    4
#define NA      1614
#define OUT_S   224
#define IM_S    448
#define PAD_S   224
#define HP_S    896

#define NPART   (BATCH*TOPN*3*OUT_S*OUT_S)   // 9,633,792
#define OFF_TIDX  NPART
#define OFF_TPROB (NPART + BATCH*TOPN)
#define OFF_SCORE (NPART + 2*BATCH*TOPN)

#define KSPLIT  9
#define NCHUNK  32
#define NP1     (BATCH*128*196)

#define N2      (BATCH*128*49)
#define N3      (BATCH*128*16)

// ---------------- scratch ----------------
__device__ float g_part1[(size_t)KSPLIT * NP1];
__device__ float g_d1[NP1];
__device__ float g_p2[(size_t)9 * N2];
__device__ float g_d2[N2];
__device__ float g_p3[(size_t)9 * N3];
__device__ float g_d3[N3];
__device__ float g_score[BATCH*NA];
__device__ int   g_topidx[BATCH*TOPN];

// bf16 hi/lo prepped operands (zero-initialized; plane borders stay zero)
__device__ __nv_bfloat16 g_wh[(size_t)9 * 128 * 2048];
__device__ __nv_bfloat16 g_wl[(size_t)9 * 128 * 2048];
__device__ __nv_bfloat16 g_ih[(size_t)BATCH * 288 * 2048];
__device__ __nv_bfloat16 g_il[(size_t)BATCH * 288 * 2048];
__device__ __nv_bfloat16 g_w2h[(size_t)9 * 128 * 128];
__device__ __nv_bfloat16 g_w2l[(size_t)9 * 128 * 128];
__device__ __nv_bfloat16 g_w3h[(size_t)9 * 128 * 128];
__device__ __nv_bfloat16 g_w3l[(size_t)9 * 128 * 128];
__device__ __nv_bfloat16 g_d1h[(size_t)BATCH * 256 * 128];
__device__ __nv_bfloat16 g_d1l[(size_t)BATCH * 256 * 128];
__device__ __nv_bfloat16 g_d2h[(size_t)BATCH * 256 * 128];
__device__ __nv_bfloat16 g_d2l[(size_t)BATCH * 256 * 128];

__device__ __forceinline__ float neg_inf() { return __int_as_float(0xff800000); }

__device__ __forceinline__ uint32_t smem_to_u32(const void* p) {
    uint32_t a;
    asm("{ .reg .u64 t; cvta.to.shared.u64 t, %1; cvt.u32.u64 %0, t; }"
        : "=r"(a) : "l"(p));
    return a;
}
__device__ __forceinline__ void cpa16(uint32_t dst, const void* src) {
    asm volatile("cp.async.cg.shared.global [%0], [%1], 16;"
                 :: "r"(dst), "l"(src) : "memory");
}
__device__ __forceinline__ void ldsm_x4(uint32_t& r0, uint32_t& r1, uint32_t& r2, uint32_t& r3,
                                        uint32_t addr) {
    asm volatile("ldmatrix.sync.aligned.m8n8.x4.shared.b16 {%0,%1,%2,%3}, [%4];"
                 : "=r"(r0), "=r"(r1), "=r"(r2), "=r"(r3) : "r"(addr));
}
__device__ __forceinline__ void ldsm_x2(uint32_t& r0, uint32_t& r1, uint32_t addr) {
    asm volatile("ldmatrix.sync.aligned.m8n8.x2.shared.b16 {%0,%1}, [%2];"
                 : "=r"(r0), "=r"(r1) : "r"(addr));
}
__device__ __forceinline__ void mma16816(float* c, uint32_t a0, uint32_t a1, uint32_t a2,
                                         uint32_t a3, uint32_t b0, uint32_t b1) {
    asm volatile("mma.sync.aligned.m16n8k16.row.col.f32.bf16.bf16.f32 "
                 "{%0,%1,%2,%3}, {%4,%5,%6,%7}, {%8,%9}, {%0,%1,%2,%3};"
                 : "+f"(c[0]), "+f"(c[1]), "+f"(c[2]), "+f"(c[3])
                 : "r"(a0), "r"(a1), "r"(a2), "r"(a3), "r"(b0), "r"(b1));
}
__device__ __forceinline__ void bfsplit(float v, __nv_bfloat16& h, __nv_bfloat16& l) {
    h = __float2bfloat16_rn(v);
    l = __float2bfloat16_rn(v - __bfloat162float(h));
}
__device__ __forceinline__ uint32_t pkbf(__nv_bfloat16 a, __nv_bfloat16 b) {
    return (uint32_t)__bfloat16_as_ushort(a) | ((uint32_t)__bfloat16_as_ushort(b) << 16);
}

// ====== prep_all: weights (blocks 0..1151) + input planes (1152..2175) ====
__global__ void prep_all(const float* __restrict__ w1,
                         const float* __restrict__ w2,
                         const float* __restrict__ w3,
                         const float* __restrict__ in)
{
    int blk = blockIdx.x;
    if (blk < 1024) {
        int idx = blk * 256 + threadIdx.x;
        int oc = idx >> 11, ic = idx & 2047;
        const float* src = w1 + (size_t)oc * 18432 + (size_t)ic * 9;
#pragma unroll
        for (int t = 0; t < 9; t++) {
            __nv_bfloat16 h, l;
            bfsplit(__ldg(&src[t]), h, l);
            size_t d = ((size_t)t * 128 + oc) * 2048 + ic;
            g_wh[d] = h; g_wl[d] = l;
        }
    } else if (blk < 1152) {
        int idx = (blk - 1024) * 256 + threadIdx.x;
        int which = idx >> 14, r = idx & 16383;
        int oc = r >> 7, ic = r & 127;
        const float* src = (which ? w3 : w2) + (size_t)(oc * 128 + ic) * 9;
        __nv_bfloat16* dh = which ? g_w3h : g_w2h;
        __nv_bfloat16* dl = which ? g_w3l : g_w2l;
#pragma unroll
        for (int t = 0; t < 9; t++) {
            __nv_bfloat16 h, l;
            bfsplit(__ldg(&src[t]), h, l);
            size_t d = ((size_t)t * 128 + oc) * 128 + ic;
            dh[d] = h; dl[d] = l;
        }
    } else {
        __shared__ float s_in[32][197];
        int iidx = blk - 1152;
        const int icb = iidx & 63;
        const int b   = iidx >> 6;
        const int tid = threadIdx.x;

        const float* src = in + ((size_t)b * 2048 + icb * 32) * 196;
        for (int i = tid; i < 32 * 196; i += 256)
            s_in[i / 196][i % 196] = __ldg(&src[i]);
        __syncthreads();

        for (int i = tid; i < 288 * 16; i += 256) {
            int pos = i >> 4, icp = i & 15;
            int py = pos / 18, px = pos % 18;
            int iy = py - 1, ix = px - 1;
            float v0 = 0.f, v1 = 0.f;
            if ((unsigned)iy < 14u && (unsigned)ix < 14u) {
                v0 = s_in[icp * 2][iy * 14 + ix];
                v1 = s_in[icp * 2 + 1][iy * 14 + ix];
            }
            __nv_bfloat16 h0, l0, h1, l1;
            bfsplit(v0, h0, l0); bfsplit(v1, h1, l1);
            size_t d = ((size_t)b * 288 + pos) * 2048 + icb * 32 + icp * 2;
            *(uint32_t*)&g_ih[d] = pkbf(h0, h1);
            *(uint32_t*)&g_il[d] = pkbf(l0, l1);
        }
    }
}

// ================= conv1 via mma.sync: N=208 (26 tiles), 256 threads ======
// Round-13 configuration (measured 125.9us, tensor 61.3%). Grid (9,16).
// M=128, N=208 (196 valid, linear n=p), K=2048, 32 chunks of 64 ic.
#define SA_H   0
#define SA_L   18432
#define SB_H   36864
#define SB_L   66816
#define STG_SZ 96768
#define SM_TOT (2 * STG_SZ)

__global__ void __launch_bounds__(256) conv1_mma()
{
    extern __shared__ __align__(16) char smem[];
    const uint32_t sb = smem_to_u32(smem);
    const int tid = threadIdx.x, wid = tid >> 5, lane = tid & 31;
    const int t = blockIdx.x, b = blockIdx.y;
    const int dy = t / 3 - 1, dx = t % 3 - 1;

    const int mrow = wid & 3;    // oc 32-block
    const int ncol = wid >> 2;   // 104-wide n block (13 tiles)

    float acc[2][13][4];
#pragma unroll
    for (int mt = 0; mt < 2; mt++)
#pragma unroll
        for (int nt = 0; nt < 13; nt++)
#pragma unroll
            for (int i = 0; i < 4; i++) acc[mt][nt][i] = 0.f;

    const __nv_bfloat16* ah0 = g_wh + ((size_t)t * 128) * 2048;
    const __nv_bfloat16* al0 = g_wl + ((size_t)t * 128) * 2048;
    const __nv_bfloat16* bh0 = g_ih + (size_t)b * 288 * 2048;
    const __nv_bfloat16* bl0 = g_il + (size_t)b * 288 * 2048;

    auto fill = [&](int stage, int c) {
        const uint32_t s0 = sb + stage * STG_SZ;
        const int kof = c * 64;
        for (int idx = tid; idx < 1024; idx += 256) {
            int row = idx >> 3, seg = idx & 7;
            uint32_t off = (uint32_t)(row * 144 + seg * 16);
            size_t so = (size_t)row * 2048 + kof + seg * 8;
            cpa16(s0 + SA_H + off, ah0 + so);
            cpa16(s0 + SA_L + off, al0 + so);
        }
        for (int idx = tid; idx < 1664; idx += 256) {
            int row = idx >> 3, seg = idx & 7;
            int pos = 0;
            if (row < 196) {
                int y = row / 14, x = row - y * 14;
                pos = (y + dy + 1) * 18 + (x + dx + 1);
            }
            uint32_t off = (uint32_t)(row * 144 + seg * 16);
            size_t so = (size_t)pos * 2048 + kof + seg * 8;
            cpa16(s0 + SB_H + off, bh0 + so);
            cpa16(s0 + SB_L + off, bl0 + so);
        }
        asm volatile("cp.async.commit_group;" ::: "memory");
    };

    const uint32_t aRow = (uint32_t)(lane & 15);
    const uint32_t aHalf = (uint32_t)(lane >> 4) * 16;
    const uint32_t bRow = (uint32_t)(lane & 7);
    const uint32_t bHalf = (uint32_t)((lane >> 3) & 1) * 16;

    fill(0, 0);
    int s = 0;
    for (int c = 0; c < NCHUNK; c++) {
        asm volatile("cp.async.wait_group 0;" ::: "memory");
        __syncthreads();
        if (c + 1 < NCHUNK) fill(s ^ 1, c + 1);

        const uint32_t s0 = sb + s * STG_SZ;
#pragma unroll
        for (int kkstep = 0; kkstep < 4; kkstep++) {
            const uint32_t kb = (uint32_t)kkstep * 32;
            uint32_t ah[2][4], al[2][4];
#pragma unroll
            for (int mt = 0; mt < 2; mt++) {
                uint32_t ra = (uint32_t)((mrow * 32 + mt * 16 + aRow) * 144) + kb + aHalf;
                ldsm_x4(ah[mt][0], ah[mt][1], ah[mt][2], ah[mt][3], s0 + SA_H + ra);
                ldsm_x4(al[mt][0], al[mt][1], al[mt][2], al[mt][3], s0 + SA_L + ra);
            }
#pragma unroll
            for (int nt = 0; nt < 13; nt++) {
                uint32_t rb = (uint32_t)((ncol * 104 + nt * 8 + bRow) * 144) + kb + bHalf;
                uint32_t bhr0, bhr1, blr0, blr1;
                ldsm_x2(bhr0, bhr1, s0 + SB_H + rb);
                ldsm_x2(blr0, blr1, s0 + SB_L + rb);
#pragma unroll
                for (int mt = 0; mt < 2; mt++) {
                    mma16816(acc[mt][nt], ah[mt][0], ah[mt][1], ah[mt][2], ah[mt][3], bhr0, bhr1);
                    mma16816(acc[mt][nt], ah[mt][0], ah[mt][1], ah[mt][2], ah[mt][3], blr0, blr1);
                    mma16816(acc[mt][nt], al[mt][0], al[mt][1], al[mt][2], al[mt][3], bhr0, bhr1);
                }
            }
        }
        s ^= 1;
        __syncthreads();
    }

    const int r = lane >> 2, q = lane & 3;
    float* pp = g_part1 + (size_t)t * NP1 + ((size_t)b * 128) * 196;
#pragma unroll
    for (int mt = 0; mt < 2; mt++) {
        int oc0 = mrow * 32 + mt * 16 + r;
#pragma unroll
        for (int nt = 0; nt < 13; nt++) {
            int n0 = ncol * 104 + nt * 8 + 2 * q;
            if (n0 < 196) {
                pp[(size_t)oc0 * 196 + n0]       = acc[mt][nt][0];
                pp[(size_t)(oc0 + 8) * 196 + n0] = acc[mt][nt][2];
            }
            if (n0 + 1 < 196) {
                pp[(size_t)oc0 * 196 + n0 + 1]       = acc[mt][nt][1];
                pp[(size_t)(oc0 + 8) * 196 + n0 + 1] = acc[mt][nt][3];
            }
        }
    }
}

// ====== finalize1: split-K reduce + bias + relu + write d1 planes =========
__global__ void finalize1_kernel(const float* __restrict__ bias)
{
    int n = blockIdx.x * 256 + threadIdx.x;
    if (n >= NP1) return;
    float s = 0.f;
#pragma unroll
    for (int k = 0; k < KSPLIT; k++) s += g_part1[(size_t)k * NP1 + n];
    int p = n % 196;
    int oc = (n / 196) & 127;
    int b = n / (196 * 128);
    float v = fmaxf(s + __ldg(&bias[oc]), 0.f);
    g_d1[n] = v;
    int pos = (p / 14 + 1) * 16 + (p % 14 + 1);
    __nv_bfloat16 h, l;
    bfsplit(v, h, l);
    size_t d = ((size_t)b * 256 + pos) * 128 + oc;
    g_d1h[d] = h;
    g_d1l[d] = l;
}

// ================= conv23_mma =============================================
#define C23_A_H  0
#define C23_A_L  34816
#define C23_B_H  69632
#define C23_B_L  87040
#define C23_TOT  104448

__global__ void __launch_bounds__(256) conv23_mma(const __nv_bfloat16* __restrict__ wh,
                                                  const __nv_bfloat16* __restrict__ wl,
                                                  const __nv_bfloat16* __restrict__ inh,
                                                  const __nv_bfloat16* __restrict__ inl,
                                                  float* __restrict__ part,
                                                  int OW, int NVALID)
{
    extern __shared__ __align__(16) char smem[];
    const uint32_t sb = smem_to_u32(smem);
    const int tid = threadIdx.x, wid = tid >> 5, lane = tid & 31;
    const int t = blockIdx.x, b = blockIdx.y;
    const int dy = t / 3 - 1, dx = t % 3 - 1;
    const int mrow = wid & 3;
    const int ncol = wid >> 2;

    const __nv_bfloat16* ah0 = wh + (size_t)t * 128 * 128;
    const __nv_bfloat16* al0 = wl + (size_t)t * 128 * 128;
    const __nv_bfloat16* bh0 = inh + (size_t)b * 256 * 128;
    const __nv_bfloat16* bl0 = inl + (size_t)b * 256 * 128;

    for (int idx = tid; idx < 2048; idx += 256) {
        int row = idx >> 4, seg = idx & 15;
        uint32_t off = (uint32_t)(row * 272 + seg * 16);
        size_t so = (size_t)row * 128 + seg * 8;
        cpa16(sb + C23_A_H + off, ah0 + so);
        cpa16(sb + C23_A_L + off, al0 + so);
    }
    for (int idx = tid; idx < 1024; idx += 256) {
        int row = idx >> 4, seg = idx & 15;
        int pos = 0;
        if (row < NVALID) {
            int oy = row / OW, ox = row % OW;
            pos = (2 * oy + dy + 1) * 16 + (2 * ox + dx + 1);
        }
        uint32_t off = (uint32_t)(row * 272 + seg * 16);
        size_t so = (size_t)pos * 128 + seg * 8;
        cpa16(sb + C23_B_H + off, bh0 + so);
        cpa16(sb + C23_B_L + off, bl0 + so);
    }
    asm volatile("cp.async.commit_group;" ::: "memory");
    asm volatile("cp.async.wait_group 0;" ::: "memory");
    __syncthreads();

    float acc[2][4][4];
#pragma unroll
    for (int mt = 0; mt < 2; mt++)
#pragma unroll
        for (int nt = 0; nt < 4; nt++)
#pragma unroll
            for (int i = 0; i < 4; i++) acc[mt][nt][i] = 0.f;

    const uint32_t aRow = (uint32_t)(lane & 15);
    const uint32_t aHalf = (uint32_t)(lane >> 4) * 16;
    const uint32_t bRow = (uint32_t)(lane & 7);
    const uint32_t bHalf = (uint32_t)((lane >> 3) & 1) * 16;

#pragma unroll
    for (int kkstep = 0; kkstep < 8; kkstep++) {
        const uint32_t kb = (uint32_t)kkstep * 32;
        uint32_t ah[2][4], al[2][4];
#pragma unroll
        for (int mt = 0; mt < 2; mt++) {
            uint32_t ra = (uint32_t)((mrow * 32 + mt * 16 + aRow) * 272) + kb + aHalf;
            ldsm_x4(ah[mt][0], ah[mt][1], ah[mt][2], ah[mt][3], sb + C23_A_H + ra);
            ldsm_x4(al[mt][0], al[mt][1], al[mt][2], al[mt][3], sb + C23_A_L + ra);
        }
#pragma unroll
        for (int nt = 0; nt < 4; nt++) {
            uint32_t rb = (uint32_t)((ncol * 32 + nt * 8 + bRow) * 272) + kb + bHalf;
            uint32_t bhr0, bhr1, blr0, blr1;
            ldsm_x2(bhr0, bhr1, sb + C23_B_H + rb);
            ldsm_x2(blr0, blr1, sb + C23_B_L + rb);
#pragma unroll
            for (int mt = 0; mt < 2; mt++) {
                mma16816(acc[mt][nt], ah[mt][0], ah[mt][1], ah[mt][2], ah[mt][3], bhr0, bhr1);
                mma16816(acc[mt][nt], ah[mt][0], ah[mt][1], ah[mt][2], ah[mt][3], blr0, blr1);
                mma16816(acc[mt][nt], al[mt][0], al[mt][1], al[mt][2], al[mt][3], bhr0, bhr1);
            }
        }
    }

    const int r = lane >> 2, q = lane & 3;
    float* pp = part + ((size_t)t * BATCH + b) * 128 * NVALID;
#pragma unroll
    for (int mt = 0; mt < 2; mt++) {
        int oc0 = mrow * 32 + mt * 16 + r;
#pragma unroll
        for (int nt = 0; nt < 4; nt++) {
            int n0 = ncol * 32 + nt * 8 + 2 * q;
            if (n0 < NVALID) {
                pp[(size_t)oc0 * NVALID + n0]       = acc[mt][nt][0];
                pp[(size_t)(oc0 + 8) * NVALID + n0] = acc[mt][nt][2];
            }
            if (n0 + 1 < NVALID) {
                pp[(size_t)oc0 * NVALID + n0 + 1]       = acc[mt][nt][1];
                pp[(size_t)(oc0 + 8) * NVALID + n0 + 1] = acc[mt][nt][3];
            }
        }
    }
}

// ====== reduce2: 9-way reduce + bias + relu + write d2 planes =============
__global__ void reduce2_kernel(const float* __restrict__ bias)
{
    int n = blockIdx.x * 256 + threadIdx.x;
    if (n >= N2) return;
    float s = __ldg(&bias[(n / 49) & 127]);
#pragma unroll
    for (int k = 0; k < 9; k++) s += g_p2[(size_t)k * N2 + n];
    float v = fmaxf(s, 0.f);
    g_d2[n] = v;
    int p = n % 49;
    int oc = (n / 49) & 127;
    int b = n / (49 * 128);
    int pos = (p / 7 + 1) * 16 + (p % 7 + 1);
    __nv_bfloat16 h, l;
    bfsplit(v, h, l);
    size_t d = ((size_t)b * 256 + pos) * 128 + oc;
    g_d2h[d] = h;
    g_d2l[d] = l;
}

__global__ void reduce3_kernel(const float* __restrict__ bias)
{
    int n = blockIdx.x * 256 + threadIdx.x;
    if (n >= N3) return;
    float s = __ldg(&bias[(n / 16) & 127]);
#pragma unroll
    for (int k = 0; k < 9; k++) s += g_p3[(size_t)k * N3 + n];
    g_d3[n] = fmaxf(s, 0.f);
}

// ================= tidy 1x1 convs -> concatenated scores =================
__global__ void tidy_kernel(const float* __restrict__ wt1, const float* __restrict__ bt1,
                            const float* __restrict__ wt2, const float* __restrict__ bt2,
                            const float* __restrict__ wt3, const float* __restrict__ bt3,
                            float* __restrict__ out)
{
    int n = blockIdx.x * 256 + threadIdx.x;
    if (n >= BATCH * NA) return;
    int b = n / NA, j = n % NA;
    const float* src; const float* wt; float bias; int c, p, stride;
    if (j < 1176) {
        c = j / 196; p = j % 196;
        src = g_d1 + (size_t)b * 128 * 196; stride = 196;
        wt = wt1; bias = __ldg(&bt1[c]);
    } else if (j < 1470) {
        int jj = j - 1176; c = jj / 49; p = jj % 49;
        src = g_d2 + (size_t)b * 128 * 49; stride = 49;
        wt = wt2; bias = __ldg(&bt2[c]);
    } else {
        int jj = j - 1470; c = jj / 16; p = jj % 16;
        src = g_d3 + (size_t)b * 128 * 16; stride = 16;
        wt = wt3; bias = __ldg(&bt3[c]);
    }
    const float4* wv = (const float4*)(wt + (size_t)c * 128);
    float a0 = 0.f, a1 = 0.f, a2 = 0.f, a3 = 0.f;
#pragma unroll 8
    for (int i = 0; i < 32; i++) {
        float4 w4 = __ldg(&wv[i]);
        int ic = 4 * i;
        a0 = fmaf(src[(size_t)(ic + 0) * stride + p], w4.x, a0);
        a1 = fmaf(src[(size_t)(ic + 1) * stride + p], w4.y, a1);
        a2 = fmaf(src[(size_t)(ic + 2) * stride + p], w4.z, a2);
        a3 = fmaf(src[(size_t)(ic + 3) * stride + p], w4.w, a3);
    }
    float acc = bias + ((a0 + a1) + (a2 + a3));
    g_score[n] = acc;
    out[OFF_SCORE + n] = acc;
}

// ================= greedy NMS (warp-shuffle reduction) =====================
__global__ void nms_kernel(const int* __restrict__ anchors, float* __restrict__ out)
{
    int b = blockIdx.x, tid = threadIdx.x;
    const int lane = tid & 31, warp = tid >> 5;
    __shared__ float s[NA];
    __shared__ float swv[8];
    __shared__ int   swi[8];
    __shared__ float pbox[4];
    __shared__ float parea;

    for (int j = tid; j < NA; j += 256) s[j] = g_score[b * NA + j];
    __syncthreads();

    for (int k = 0; k < TOPN; k++) {
        float bv = neg_inf(); int bi = 0x7fffffff;
        for (int j = tid; j < NA; j += 256) {
            float v = s[j];
            if (v > bv || (v == bv && j < bi)) { bv = v; bi = j; }
        }
#pragma unroll
        for (int off = 16; off > 0; off >>= 1) {
            float v2 = __shfl_down_sync(0xffffffff, bv, off);
            int   i2 = __shfl_down_sync(0xffffffff, bi, off);
            if (v2 > bv || (v2 == bv && i2 < bi)) { bv = v2; bi = i2; }
        }
        if (lane == 0) { swv[warp] = bv; swi[warp] = bi; }
        __syncthreads();
        if (tid == 0) {
            float fv = swv[0]; int fi = swi[0];
#pragma unroll
            for (int w = 1; w < 8; w++) {
                float v2 = swv[w]; int i2 = swi[w];
                if (v2 > fv || (v2 == fv && i2 < fi)) { fv = v2; fi = i2; }
            }
            const int* a = anchors + (size_t)fi * 4;
            pbox[0] = (float)a[0]; pbox[1] = (float)a[1];
            pbox[2] = (float)a[2]; pbox[3] = (float)a[3];
            parea = (pbox[2] - pbox[0]) * (pbox[3] - pbox[1]);
            g_topidx[b * TOPN + k] = fi;
            out[OFF_TIDX  + b * TOPN + k] = (float)fi;
            out[OFF_TPROB + b * TOPN + k] = fv;
        }
        __syncthreads();
        float y0 = pbox[0], x0 = pbox[1], y1 = pbox[2], x1 = pbox[3], pa = parea;
        for (int j = tid; j < NA; j += 256) {
            const int* a = anchors + (size_t)j * 4;
            float ay0 = (float)a[0], ax0 = (float)a[1];
            float ay1 = (float)a[2], ax1 = (float)a[3];
            float iy = fmaxf(fminf(ay1, y1) - fmaxf(ay0, y0), 0.f);
            float ix = fmaxf(fminf(ax1, x1) - fmaxf(ax0, x0), 0.f);
            float inter = iy * ix;
            float area  = (ay1 - ay0) * (ax1 - ax0);
            float iou = inter / (area + pa - inter);
            if (iou >= 0.25f) s[j] = neg_inf();
        }
        __syncthreads();
    }
}

// ================= crop + bilinear resize =================================
__device__ __forceinline__ float fetchpix(const float* __restrict__ xb, int yy, int xx)
{
    yy -= PAD_S; xx -= PAD_S;
    if ((unsigned)yy < (unsigned)IM_S && (unsigned)xx < (unsigned)IM_S)
        return __ldg(&xb[(size_t)yy * IM_S + xx]);
    return 0.f;
}

__global__ void crop_kernel(const float* __restrict__ x,
                            const int* __restrict__ anchors,
                            float* __restrict__ out)
{
    const int crop = blockIdx.x;
    const int oy   = blockIdx.y;
    const int ox   = threadIdx.x;
    const int b    = crop >> 2;

    const int pick = g_topidx[crop];
    const int* a = anchors + (size_t)pick * 4;
    float y0 = (float)a[0], x0 = (float)a[1], y1 = (float)a[2], x1 = (float)a[3];

    float ty = (float)oy / 223.0f;
    float tx = (float)ox / 223.0f;
    float ys = y0 + ty * (y1 - y0 - 1.0f);
    float xs = x0 + tx * (x1 - x0 - 1.0f);
    int yi0 = (int)floorf(ys); int yi1 = min(yi0 + 1, HP_S - 1);
    int xi0 = (int)floorf(xs); int xi1 = min(xi0 + 1, HP_S - 1);
    float wy = ys - (float)yi0;
    float wx = xs - (float)xi0;
    float c00 = (1.f - wy) * (1.f - wx);
    float c01 = (1.f - wy) * wx;
    float c10 = wy * (1.f - wx);
    float c11 = wy * wx;

#pragma unroll
    for (int c = 0; c < 3; c++) {
        const float* xb = x + ((size_t)b * 3 + c) * IM_S * IM_S;
        float v = fetchpix(xb, yi0, xi0) * c00
                + fetchpix(xb, yi0, xi1) * c01
                + fetchpix(xb, yi1, xi0) * c10
                + fetchpix(xb, yi1, xi1) * c11;
        out[(((size_t)crop * 3 + c) * OUT_S + oy) * OUT_S + ox] = v;
    }
}

// =========================================================================
extern "C" void kernel_launch(void* const* d_in, const int* in_sizes, int n_in,
                              void* d_out, int out_size)
{
    const float* x    = (const float*)d_in[0];
    const float* rpn  = (const float*)d_in[1];
    const float* w1   = (const float*)d_in[2];
    const float* b1   = (const float*)d_in[3];
    const float* w2   = (const float*)d_in[4];
    const float* b2   = (const float*)d_in[5];
    const float* w3   = (const float*)d_in[6];
    const float* b3   = (const float*)d_in[7];
    const float* wt1  = (const float*)d_in[8];
    const float* bt1  = (const float*)d_in[9];
    const float* wt2  = (const float*)d_in[10];
    const float* bt2  = (const float*)d_in[11];
    const float* wt3  = (const float*)d_in[12];
    const float* bt3  = (const float*)d_in[13];
    const int*   anc  = (const int*)d_in[14];
    float* out = (float*)d_out;

    cudaFuncSetAttribute(conv1_mma, cudaFuncAttributeMaxDynamicSharedMemorySize, SM_TOT);
    cudaFuncSetAttribute(conv23_mma, cudaFuncAttributeMaxDynamicSharedMemorySize, C23_TOT);

    float *p2, *p3;
    cudaGetSymbolAddress((void**)&p2, g_p2);
    cudaGetSymbolAddress((void**)&p3, g_p3);
    __nv_bfloat16 *w2h, *w2l, *w3h, *w3l, *d1h, *d1l, *d2h, *d2l;
    cudaGetSymbolAddress((void**)&w2h, g_w2h);
    cudaGetSymbolAddress((void**)&w2l, g_w2l);
    cudaGetSymbolAddress((void**)&w3h, g_w3h);
    cudaGetSymbolAddress((void**)&w3l, g_w3l);
    cudaGetSymbolAddress((void**)&d1h, g_d1h);
    cudaGetSymbolAddress((void**)&d1l, g_d1l);
    cudaGetSymbolAddress((void**)&d2h, g_d2h);
    cudaGetSymbolAddress((void**)&d2l, g_d2l);

    prep_all<<<2176, 256>>>(w1, w2, w3, rpn);

    conv1_mma<<<dim3(KSPLIT, BATCH), 256, SM_TOT>>>();
    finalize1_kernel<<<(NP1 + 255) / 256, 256>>>(b1);

    conv23_mma<<<dim3(9, BATCH), 256, C23_TOT>>>(w2h, w2l, d1h, d1l, p2, 7, 49);  // ncu slot
    reduce2_kernel<<<(N2 + 255) / 256, 256>>>(b2);

    conv23_mma<<<dim3(9, BATCH), 256, C23_TOT>>>(w3h, w3l, d2h, d2l, p3, 4, 16);
    reduce3_kernel<<<(N3 + 255) / 256, 256>>>(b3);

    tidy_kernel<<<(BATCH * NA + 255) / 256, 256>>>(wt1, bt1, wt2, bt2, wt3, bt3, out);
    nms_kernel<<<BATCH, 256>>>(anc, out);
    crop_kernel<<<dim3(BATCH * TOPN, OUT_S), OUT_S>>>(x, anc, out);
}